// round 1
// baseline (speedup 1.0000x reference)
#include <cuda_runtime.h>
#include <math.h>

#define BB   2
#define SS   2048
#define DD   1024
#define HH   16
#define DK   64
#define MM   (BB*SS)          // 4096
#define NEGV (-1000000000.0f)
#define SCALE 0.125f          // 1/sqrt(64)

// ---------------- scratch (no cudaMalloc allowed) ----------------
__device__ float g_q[BB*SS*DD];
__device__ float g_k[BB*SS*DD];
__device__ float g_v[BB*SS*DD];
__device__ float g_x[BB*SS*DD];

// ---------------- GEMM: C = A @ W^T + bias ----------------
// A[M,K] row-major, W[N,K] row-major (TN layout), C[M,N].
// Up to 3 independent (A,W,b,C) problems selected by blockIdx.z.
#define GBM 128
#define GBN 128
#define GBK 16

__global__ __launch_bounds__(256, 2) void gemm_tn(
    const float* __restrict__ A0, const float* __restrict__ A1, const float* __restrict__ A2,
    const float* __restrict__ W0, const float* __restrict__ W1, const float* __restrict__ W2,
    const float* __restrict__ b0, const float* __restrict__ b1, const float* __restrict__ b2,
    float* __restrict__ C0, float* __restrict__ C1, float* __restrict__ C2,
    int M, int N, int K)
{
    const int z = blockIdx.z;
    const float* __restrict__ A    = (z == 0) ? A0 : (z == 1) ? A1 : A2;
    const float* __restrict__ W    = (z == 0) ? W0 : (z == 1) ? W1 : W2;
    const float* __restrict__ bias = (z == 0) ? b0 : (z == 1) ? b1 : b2;
    float* __restrict__ C          = (z == 0) ? C0 : (z == 1) ? C1 : C2;

    __shared__ float As[GBK][GBM];
    __shared__ float Bs[GBK][GBN];

    const int tid = threadIdx.x;
    const int m0 = blockIdx.y * GBM;
    const int n0 = blockIdx.x * GBN;
    const int ty = tid >> 4;      // 0..15
    const int tx = tid & 15;      // 0..15

    float acc[8][8];
    #pragma unroll
    for (int i = 0; i < 8; ++i)
        #pragma unroll
        for (int j = 0; j < 8; ++j) acc[i][j] = 0.f;

    for (int k0 = 0; k0 < K; k0 += GBK) {
        // cooperative load: 128 rows x 16 k for both tiles, float4 per thread x2
        #pragma unroll
        for (int l = 0; l < 2; ++l) {
            int idx = tid + l * 256;          // 0..511
            int row = idx >> 2;               // 0..127
            int kq  = (idx & 3) << 2;         // 0,4,8,12
            float4 va = *(const float4*)&A[(size_t)(m0 + row) * K + k0 + kq];
            As[kq + 0][row] = va.x; As[kq + 1][row] = va.y;
            As[kq + 2][row] = va.z; As[kq + 3][row] = va.w;
            float4 vb = *(const float4*)&W[(size_t)(n0 + row) * K + k0 + kq];
            Bs[kq + 0][row] = vb.x; Bs[kq + 1][row] = vb.y;
            Bs[kq + 2][row] = vb.z; Bs[kq + 3][row] = vb.w;
        }
        __syncthreads();

        #pragma unroll
        for (int kk = 0; kk < GBK; ++kk) {
            float a[8], b[8];
            #pragma unroll
            for (int i = 0; i < 8; ++i) a[i] = As[kk][ty * 8 + i];
            #pragma unroll
            for (int j = 0; j < 8; ++j) b[j] = Bs[kk][tx * 8 + j];
            #pragma unroll
            for (int i = 0; i < 8; ++i)
                #pragma unroll
                for (int j = 0; j < 8; ++j)
                    acc[i][j] = fmaf(a[i], b[j], acc[i][j]);
        }
        __syncthreads();
    }

    float bv[8];
    #pragma unroll
    for (int j = 0; j < 8; ++j) bv[j] = bias[n0 + tx * 8 + j];

    #pragma unroll
    for (int i = 0; i < 8; ++i) {
        int m = m0 + ty * 8 + i;
        float* crow = &C[(size_t)m * N + n0 + tx * 8];
        float4 w0, w1;
        w0.x = acc[i][0] + bv[0]; w0.y = acc[i][1] + bv[1];
        w0.z = acc[i][2] + bv[2]; w0.w = acc[i][3] + bv[3];
        w1.x = acc[i][4] + bv[4]; w1.y = acc[i][5] + bv[5];
        w1.z = acc[i][6] + bv[6]; w1.w = acc[i][7] + bv[7];
        *(float4*)&crow[0] = w0;
        *(float4*)&crow[4] = w1;
    }
}

// ---------------- Flash attention (fp32, one thread = one query row) ----------------
// Q/K/V stored as [B, S, D]; head h uses columns [h*DK, (h+1)*DK).
#define FBM 128   // query rows per block = threads per block
#define FBN 64    // key tile

// dynamic smem layout: Ks[64*64] | Vs[64*64] | ssc[128*(FBN+1)] | msk[64]
#define FLASH_SMEM ((FBN*DK + FBN*DK + FBM*(FBN+1)) * sizeof(float) + FBN * sizeof(int))

__global__ __launch_bounds__(FBM) void flash_attn(
    const float* __restrict__ Q, const float* __restrict__ K,
    const float* __restrict__ V, const int* __restrict__ mask,
    float* __restrict__ X)
{
    extern __shared__ float fsm[];
    float* Ks  = fsm;
    float* Vs  = Ks + FBN * DK;
    float* ssc = Vs + FBN * DK;
    int*   msk = (int*)(ssc + FBM * (FBN + 1));

    const int qr = threadIdx.x;
    const int qt = blockIdx.x;
    const int h  = blockIdx.y;
    const int b  = blockIdx.z;

    const int row = b * SS + qt * FBM + qr;
    const float* qptr = &Q[(size_t)row * DD + h * DK];

    float q[DK], o[DK];
    #pragma unroll
    for (int d = 0; d < DK; d += 4) {
        float4 t = *(const float4*)&qptr[d];
        q[d] = t.x; q[d + 1] = t.y; q[d + 2] = t.z; q[d + 3] = t.w;
        o[d] = 0.f; o[d + 1] = 0.f; o[d + 2] = 0.f; o[d + 3] = 0.f;
    }
    float mval = -INFINITY, lval = 0.f;
    float* srow = &ssc[qr * (FBN + 1)];

    for (int kt = 0; kt < SS / FBN; ++kt) {
        __syncthreads();   // prior tile's Vs fully consumed
        const int kbase = b * SS + kt * FBN;
        // cooperative K/V tile load: 16 threads cover one 256B row -> coalesced
        #pragma unroll
        for (int l = 0; l < (FBN * DK / 4) / FBM; ++l) {
            int i  = threadIdx.x + l * FBM;
            int j  = i >> 4;
            int d4 = (i & 15) << 2;
            const size_t g = (size_t)(kbase + j) * DD + h * DK + d4;
            *(float4*)&Ks[j * DK + d4] = *(const float4*)&K[g];
            *(float4*)&Vs[j * DK + d4] = *(const float4*)&V[g];
        }
        if (threadIdx.x < FBN) msk[threadIdx.x] = mask[b * SS + kt * FBN + threadIdx.x];
        __syncthreads();

        // pass 1: scores for this row, tile max
        float tmax = -INFINITY;
        for (int j = 0; j < FBN; ++j) {
            const float* kr = &Ks[j * DK];   // broadcast across all threads
            float s0 = 0.f, s1 = 0.f, s2 = 0.f, s3 = 0.f;
            #pragma unroll
            for (int d = 0; d < DK; d += 4) {
                s0 = fmaf(q[d + 0], kr[d + 0], s0);
                s1 = fmaf(q[d + 1], kr[d + 1], s1);
                s2 = fmaf(q[d + 2], kr[d + 2], s2);
                s3 = fmaf(q[d + 3], kr[d + 3], s3);
            }
            float s = ((s0 + s1) + (s2 + s3)) * SCALE;
            s = msk[j] ? s : NEGV;
            srow[j] = s;
            tmax = fmaxf(tmax, s);
        }

        // pass 2: online softmax rescale + PV accumulate
        float mnew  = fmaxf(mval, tmax);
        float alpha = __expf(mval - mnew);
        lval *= alpha;
        #pragma unroll
        for (int d = 0; d < DK; ++d) o[d] *= alpha;

        for (int j = 0; j < FBN; ++j) {
            float p = __expf(srow[j] - mnew);
            lval += p;
            const float* vr = &Vs[j * DK];   // broadcast
            #pragma unroll
            for (int d = 0; d < DK; ++d)
                o[d] = fmaf(p, vr[d], o[d]);
        }
        mval = mnew;
    }

    const float inv = 1.f / lval;
    float* xptr = &X[(size_t)row * DD + h * DK];
    #pragma unroll
    for (int d = 0; d < DK; d += 4) {
        float4 t;
        t.x = o[d] * inv; t.y = o[d + 1] * inv;
        t.z = o[d + 2] * inv; t.w = o[d + 3] * inv;
        *(float4*)&xptr[d] = t;
    }
}

// ---------------- launch ----------------
extern "C" void kernel_launch(void* const* d_in, const int* in_sizes, int n_in,
                              void* d_out, int out_size)
{
    const float* query = (const float*)d_in[0];
    const float* key   = (const float*)d_in[1];
    const float* value = (const float*)d_in[2];
    const int*   mask  = (const int*)  d_in[3];
    const float* wq = (const float*)d_in[4];
    const float* bq = (const float*)d_in[5];
    const float* wk = (const float*)d_in[6];
    const float* bk = (const float*)d_in[7];
    const float* wv = (const float*)d_in[8];
    const float* bv = (const float*)d_in[9];
    const float* wo = (const float*)d_in[10];
    const float* bo = (const float*)d_in[11];
    float* out = (float*)d_out;

    float *q, *k, *v, *x;
    cudaGetSymbolAddress((void**)&q, g_q);
    cudaGetSymbolAddress((void**)&k, g_k);
    cudaGetSymbolAddress((void**)&v, g_v);
    cudaGetSymbolAddress((void**)&x, g_x);

    cudaFuncSetAttribute(flash_attn, cudaFuncAttributeMaxDynamicSharedMemorySize,
                         (int)FLASH_SMEM);

    // 1) fused QKV projections (gridDim.z selects weight set)
    dim3 gqkv(DD / GBN, MM / GBM, 3);
    gemm_tn<<<gqkv, 256>>>(query, key, value,
                           wq, wk, wv,
                           bq, bk, bv,
                           q, k, v,
                           MM, DD, DD);

    // 2) flash attention over (qtile, head, batch)
    dim3 gfa(SS / FBM, HH, BB);
    flash_attn<<<gfa, FBM, FLASH_SMEM>>>(q, k, v, mask, x);

    // 3) output projection
    dim3 go(DD / GBN, MM / GBM, 1);
    gemm_tn<<<go, 256>>>(x, x, x,
                         wo, wo, wo,
                         bo, bo, bo,
                         out, out, out,
                         MM, DD, DD);
}

// round 2
// speedup vs baseline: 3.1606x; 3.1606x over previous
#include <cuda_runtime.h>
#include <math.h>

#define BB   2
#define SS   2048
#define DD   1024
#define HH   16
#define DKK  64
#define MM   (BB*SS)          // 4096
#define NEGV (-1000000000.0f)
#define SCALE 0.125f          // 1/sqrt(64)

// ---------------- scratch (no cudaMalloc allowed) ----------------
__device__ float g_q[BB*SS*DD];
__device__ float g_k[BB*SS*DD];
__device__ float g_v[BB*SS*DD];
__device__ float g_x[BB*SS*DD];

// ---------------- helpers ----------------
__device__ __forceinline__ unsigned f2tf(float f) {
    unsigned u;
    asm("cvt.rna.tf32.f32 %0, %1;" : "=r"(u) : "f"(f));
    return u;
}

__device__ __forceinline__ void mma8(float d[4],
                                     unsigned a0, unsigned a1, unsigned a2, unsigned a3,
                                     unsigned b0, unsigned b1) {
    asm volatile(
        "mma.sync.aligned.m16n8k8.row.col.f32.tf32.tf32.f32 "
        "{%0,%1,%2,%3}, {%4,%5,%6,%7}, {%8,%9}, {%0,%1,%2,%3};"
        : "+f"(d[0]), "+f"(d[1]), "+f"(d[2]), "+f"(d[3])
        : "r"(a0), "r"(a1), "r"(a2), "r"(a3), "r"(b0), "r"(b1));
}

// ---------------- GEMM (tensor core tf32): C = A @ W^T + bias ----------------
// A[M,K] row-major, W[N,K] row-major, C[M,N]. 3 problems via blockIdx.z.
#define GBM 128
#define GBN 128
#define GBK 32
#define GSTR 36   // 32 + 4 pad: frag LDS bank = (row*4 + k) % 32 -> conflict-free

__global__ __launch_bounds__(256, 2) void gemm_tc(
    const float* __restrict__ A0, const float* __restrict__ A1, const float* __restrict__ A2,
    const float* __restrict__ W0, const float* __restrict__ W1, const float* __restrict__ W2,
    const float* __restrict__ b0p, const float* __restrict__ b1p, const float* __restrict__ b2p,
    float* __restrict__ C0, float* __restrict__ C1, float* __restrict__ C2,
    int M, int N, int K)
{
    const int z = blockIdx.z;
    const float* __restrict__ A    = (z == 0) ? A0 : (z == 1) ? A1 : A2;
    const float* __restrict__ W    = (z == 0) ? W0 : (z == 1) ? W1 : W2;
    const float* __restrict__ bias = (z == 0) ? b0p : (z == 1) ? b1p : b2p;
    float* __restrict__ C          = (z == 0) ? C0 : (z == 1) ? C1 : C2;

    __shared__ unsigned As[GBM * GSTR];
    __shared__ unsigned Ws[GBM * GSTR];

    const int tid  = threadIdx.x;
    const int lane = tid & 31;
    const int wid  = tid >> 5;
    const int wm   = (wid & 3) * 32;   // warp m offset (4 warps in M)
    const int wn   = (wid >> 2) * 64;  // warp n offset (2 warps in N)
    const int m0   = blockIdx.y * GBM;
    const int n0   = blockIdx.x * GBN;
    const int lq   = lane >> 2;        // 0..7
    const int lr   = lane & 3;         // 0..3

    float acc[2][8][4];
    #pragma unroll
    for (int mt = 0; mt < 2; ++mt)
        #pragma unroll
        for (int nt = 0; nt < 8; ++nt)
            #pragma unroll
            for (int i = 0; i < 4; ++i) acc[mt][nt][i] = 0.f;

    for (int kc = 0; kc < K; kc += GBK) {
        // cooperative load + tf32 convert: 128 rows x 8 float4 per tile
        #pragma unroll
        for (int l = 0; l < 4; ++l) {
            int idx = tid + l * 256;
            int row = idx >> 3;
            int f4  = (idx & 7) * 4;
            float4 va = *(const float4*)&A[(size_t)(m0 + row) * K + kc + f4];
            unsigned* pa = &As[row * GSTR + f4];
            pa[0] = f2tf(va.x); pa[1] = f2tf(va.y); pa[2] = f2tf(va.z); pa[3] = f2tf(va.w);
            float4 vw = *(const float4*)&W[(size_t)(n0 + row) * K + kc + f4];
            unsigned* pw = &Ws[row * GSTR + f4];
            pw[0] = f2tf(vw.x); pw[1] = f2tf(vw.y); pw[2] = f2tf(vw.z); pw[3] = f2tf(vw.w);
        }
        __syncthreads();

        #pragma unroll
        for (int ks = 0; ks < 4; ++ks) {
            const int kb = ks * 8;
            unsigned bf[8][2];
            #pragma unroll
            for (int nt = 0; nt < 8; ++nt) {
                int nrow = wn + nt * 8 + lq;
                bf[nt][0] = Ws[nrow * GSTR + kb + lr];
                bf[nt][1] = Ws[nrow * GSTR + kb + lr + 4];
            }
            #pragma unroll
            for (int mt = 0; mt < 2; ++mt) {
                int r = wm + mt * 16 + lq;
                unsigned a0 = As[r * GSTR + kb + lr];
                unsigned a1 = As[(r + 8) * GSTR + kb + lr];
                unsigned a2 = As[r * GSTR + kb + lr + 4];
                unsigned a3 = As[(r + 8) * GSTR + kb + lr + 4];
                #pragma unroll
                for (int nt = 0; nt < 8; ++nt)
                    mma8(acc[mt][nt], a0, a1, a2, a3, bf[nt][0], bf[nt][1]);
            }
        }
        __syncthreads();
    }

    // epilogue: bias + store (C layout: c0/c1 row, c2/c3 row+8, cols 2*lr, 2*lr+1)
    #pragma unroll
    for (int mt = 0; mt < 2; ++mt) {
        #pragma unroll
        for (int nt = 0; nt < 8; ++nt) {
            int row = m0 + wm + mt * 16 + lq;
            int col = n0 + wn + nt * 8 + 2 * lr;
            float bv0 = bias[col], bv1 = bias[col + 1];
            float2 v0, v1;
            v0.x = acc[mt][nt][0] + bv0; v0.y = acc[mt][nt][1] + bv1;
            v1.x = acc[mt][nt][2] + bv0; v1.y = acc[mt][nt][3] + bv1;
            *(float2*)&C[(size_t)row * N + col] = v0;
            *(float2*)&C[(size_t)(row + 8) * N + col] = v1;
        }
    }
}

// ---------------- Flash attention (tf32 tensor cores) ----------------
// Block: 64 q-rows of one (b,h); 4 warps x 16 rows. Key tiles of 64.
#define KST 68   // Ks stride: bank = (key*4 + d) % 32 -> conflict-free B-frag gather
#define VST 72   // Vs stride: bank = (key*8 + d) % 32 -> conflict-free
#define PST 68
// smem (unsigned): Ks[64*68] + Vs[64*72] + Ps[4*16*68] + msk[64]
#define FLASH_SMEM ((64*KST + 64*VST + 4*16*PST) * 4 + 64 * 4)

__global__ __launch_bounds__(128) void flash_tc(
    const float* __restrict__ Q, const float* __restrict__ K,
    const float* __restrict__ V, const int* __restrict__ mask,
    float* __restrict__ X)
{
    extern __shared__ unsigned sm[];
    unsigned* Ks = sm;
    unsigned* Vs = Ks + 64 * KST;
    unsigned* Ps = Vs + 64 * VST;
    int* msk     = (int*)(Ps + 4 * 16 * PST);

    const int tid  = threadIdx.x;
    const int lane = tid & 31;
    const int w    = tid >> 5;
    const int lq   = lane >> 2;   // 0..7
    const int lr   = lane & 3;    // 0..3

    const int qb = blockIdx.x * 64;
    const int h  = blockIdx.y;
    const int b  = blockIdx.z;

    const int r0g = b * SS + qb + w * 16 + lq;   // global row of thread's row0
    const float* Qb  = Q + (size_t)r0g * DD + h * DKK;
    const float* Qb8 = Q + (size_t)(r0g + 8) * DD + h * DKK;

    // Q fragments (pre-scaled, tf32) held in registers for whole kernel
    unsigned qf[8][4];
    #pragma unroll
    for (int kt = 0; kt < 8; ++kt) {
        int c = kt * 8 + lr;
        qf[kt][0] = f2tf(Qb[c] * SCALE);
        qf[kt][1] = f2tf(Qb8[c] * SCALE);
        qf[kt][2] = f2tf(Qb[c + 4] * SCALE);
        qf[kt][3] = f2tf(Qb8[c + 4] * SCALE);
    }

    float oacc[8][4];
    #pragma unroll
    for (int nt = 0; nt < 8; ++nt)
        #pragma unroll
        for (int i = 0; i < 4; ++i) oacc[nt][i] = 0.f;
    float mr0 = -INFINITY, mr1 = -INFINITY, l0 = 0.f, l1 = 0.f;
    unsigned* Pw = Ps + w * 16 * PST;

    for (int t = 0; t < SS / 64; ++t) {
        __syncthreads();   // prior tile fully consumed
        // load K,V tile (64 keys x 64 d), convert to tf32
        #pragma unroll
        for (int l = 0; l < 8; ++l) {
            int idx = tid + l * 128;
            int key = idx >> 4;
            int d4  = (idx & 15) * 4;
            size_t g = (size_t)(b * SS + t * 64 + key) * DD + h * DKK + d4;
            float4 kv = *(const float4*)&K[g];
            unsigned* pk = &Ks[key * KST + d4];
            pk[0] = f2tf(kv.x); pk[1] = f2tf(kv.y); pk[2] = f2tf(kv.z); pk[3] = f2tf(kv.w);
            float4 vv = *(const float4*)&V[g];
            unsigned* pv = &Vs[key * VST + d4];
            pv[0] = f2tf(vv.x); pv[1] = f2tf(vv.y); pv[2] = f2tf(vv.z); pv[3] = f2tf(vv.w);
        }
        if (tid < 64) msk[tid] = mask[b * SS + t * 64 + tid];
        __syncthreads();

        // S = Q K^T (B-frag gathers K^T directly from key-major smem)
        float sacc[8][4];
        #pragma unroll
        for (int nt = 0; nt < 8; ++nt)
            #pragma unroll
            for (int i = 0; i < 4; ++i) sacc[nt][i] = 0.f;

        #pragma unroll
        for (int ks = 0; ks < 8; ++ks) {
            const int kb = ks * 8;
            #pragma unroll
            for (int nt = 0; nt < 8; ++nt) {
                int krow = nt * 8 + lq;
                unsigned bb0 = Ks[krow * KST + kb + lr];
                unsigned bb1 = Ks[krow * KST + kb + lr + 4];
                mma8(sacc[nt], qf[ks][0], qf[ks][1], qf[ks][2], qf[ks][3], bb0, bb1);
            }
        }

        // mask + tile row max
        float tm0 = -INFINITY, tm1 = -INFINITY;
        #pragma unroll
        for (int nt = 0; nt < 8; ++nt) {
            int c0 = nt * 8 + 2 * lr;
            int mk0 = msk[c0], mk1 = msk[c0 + 1];
            if (!mk0) { sacc[nt][0] = NEGV; sacc[nt][2] = NEGV; }
            if (!mk1) { sacc[nt][1] = NEGV; sacc[nt][3] = NEGV; }
            tm0 = fmaxf(tm0, fmaxf(sacc[nt][0], sacc[nt][1]));
            tm1 = fmaxf(tm1, fmaxf(sacc[nt][2], sacc[nt][3]));
        }
        tm0 = fmaxf(tm0, __shfl_xor_sync(0xffffffffu, tm0, 1));
        tm0 = fmaxf(tm0, __shfl_xor_sync(0xffffffffu, tm0, 2));
        tm1 = fmaxf(tm1, __shfl_xor_sync(0xffffffffu, tm1, 1));
        tm1 = fmaxf(tm1, __shfl_xor_sync(0xffffffffu, tm1, 2));

        float mn0 = fmaxf(mr0, tm0), mn1 = fmaxf(mr1, tm1);
        float al0 = __expf(mr0 - mn0), al1 = __expf(mr1 - mn1);
        mr0 = mn0; mr1 = mn1;
        l0 *= al0; l1 *= al1;
        #pragma unroll
        for (int nt = 0; nt < 8; ++nt) {
            oacc[nt][0] *= al0; oacc[nt][1] *= al0;
            oacc[nt][2] *= al1; oacc[nt][3] *= al1;
        }

        // P = exp(S - m), rounded to tf32; store to per-warp smem region
        #pragma unroll
        for (int nt = 0; nt < 8; ++nt) {
            float p0 = __expf(sacc[nt][0] - mn0);
            float p1 = __expf(sacc[nt][1] - mn0);
            float p2 = __expf(sacc[nt][2] - mn1);
            float p3 = __expf(sacc[nt][3] - mn1);
            unsigned u0 = f2tf(p0), u1 = f2tf(p1), u2 = f2tf(p2), u3 = f2tf(p3);
            l0 += __uint_as_float(u0) + __uint_as_float(u1);
            l1 += __uint_as_float(u2) + __uint_as_float(u3);
            int c = nt * 8 + 2 * lr;
            uint2 s0; s0.x = u0; s0.y = u1;
            uint2 s1; s1.x = u2; s1.y = u3;
            *(uint2*)&Pw[lq * PST + c] = s0;
            *(uint2*)&Pw[(lq + 8) * PST + c] = s1;
        }
        __syncwarp();

        // O += P V
        #pragma unroll
        for (int ks = 0; ks < 8; ++ks) {
            const int kb = ks * 8;
            unsigned a0 = Pw[lq * PST + kb + lr];
            unsigned a1 = Pw[(lq + 8) * PST + kb + lr];
            unsigned a2 = Pw[lq * PST + kb + lr + 4];
            unsigned a3 = Pw[(lq + 8) * PST + kb + lr + 4];
            #pragma unroll
            for (int nt = 0; nt < 8; ++nt) {
                unsigned bb0 = Vs[(kb + lr) * VST + nt * 8 + lq];
                unsigned bb1 = Vs[(kb + lr + 4) * VST + nt * 8 + lq];
                mma8(oacc[nt], a0, a1, a2, a3, bb0, bb1);
            }
        }
    }

    // final: reduce l across quad, normalize, write
    l0 += __shfl_xor_sync(0xffffffffu, l0, 1);
    l0 += __shfl_xor_sync(0xffffffffu, l0, 2);
    l1 += __shfl_xor_sync(0xffffffffu, l1, 1);
    l1 += __shfl_xor_sync(0xffffffffu, l1, 2);
    const float inv0 = 1.f / l0, inv1 = 1.f / l1;

    #pragma unroll
    for (int nt = 0; nt < 8; ++nt) {
        int c = nt * 8 + 2 * lr;
        float2 v0, v1;
        v0.x = oacc[nt][0] * inv0; v0.y = oacc[nt][1] * inv0;
        v1.x = oacc[nt][2] * inv1; v1.y = oacc[nt][3] * inv1;
        *(float2*)&X[(size_t)r0g * DD + h * DKK + c] = v0;
        *(float2*)&X[(size_t)(r0g + 8) * DD + h * DKK + c] = v1;
    }
}

// ---------------- launch ----------------
extern "C" void kernel_launch(void* const* d_in, const int* in_sizes, int n_in,
                              void* d_out, int out_size)
{
    const float* query = (const float*)d_in[0];
    const float* key   = (const float*)d_in[1];
    const float* value = (const float*)d_in[2];
    const int*   mask  = (const int*)  d_in[3];
    const float* wq = (const float*)d_in[4];
    const float* bq = (const float*)d_in[5];
    const float* wk = (const float*)d_in[6];
    const float* bk = (const float*)d_in[7];
    const float* wv = (const float*)d_in[8];
    const float* bv = (const float*)d_in[9];
    const float* wo = (const float*)d_in[10];
    const float* bo = (const float*)d_in[11];
    float* out = (float*)d_out;

    float *q, *k, *v, *x;
    cudaGetSymbolAddress((void**)&q, g_q);
    cudaGetSymbolAddress((void**)&k, g_k);
    cudaGetSymbolAddress((void**)&v, g_v);
    cudaGetSymbolAddress((void**)&x, g_x);

    cudaFuncSetAttribute(flash_tc, cudaFuncAttributeMaxDynamicSharedMemorySize,
                         (int)FLASH_SMEM);

    // 1) fused QKV projections
    dim3 gqkv(DD / GBN, MM / GBM, 3);
    gemm_tc<<<gqkv, 256>>>(query, key, value,
                           wq, wk, wv,
                           bq, bk, bv,
                           q, k, v,
                           MM, DD, DD);

    // 2) flash attention
    dim3 gfa(SS / 64, HH, BB);
    flash_tc<<<gfa, 128, FLASH_SMEM>>>(q, k, v, mask, x);

    // 3) output projection
    dim3 go(DD / GBN, MM / GBM, 1);
    gemm_tc<<<go, 256>>>(x, x, x,
                         wo, wo, wo,
                         bo, bo, bo,
                         out, out, out,
                         MM, DD, DD);
}